// round 15
// baseline (speedup 1.0000x reference)
#include <cuda_runtime.h>
#include <cuda_fp16.h>
#include <cstdint>

// ---------------------------------------------------------------------------
// CasualSelfAttention: B=4, T=2048, C=2048, H=16, HD=128
//   qkv = x @ Wqkv (+fused RoPE, fp16 out) ; flash-attn (fp16 mma, causal) ;
//   out = y @ Wproj
// GEMMs: fp16 split GEMM (W-lo pass only on q,k columns of GEMM1).
//        CTA tile 128x128, 8 warps (2x4 of 64x32), 2 CTAs/SM -> 4 warps/SMSP.
// Flash: fp16 m16n8k16, P in registers, K via ldmatrix.x4,
//        V via ldmatrix.x4.trans, exp2-domain softmax, single sync per tile.
// ---------------------------------------------------------------------------

#define DEVINLINE __device__ __forceinline__

static constexpr int Bt = 4;
static constexpr int Tt = 2048;
static constexpr int Ct = 2048;
static constexpr int Ht = 16;
static constexpr int HDt = 128;
static constexpr int MTOT = Bt * Tt;        // 8192
static constexpr int C3 = 3 * Ct;           // 6144

// Scratch (device globals: allocation-free rule)
__device__ __half g_qkv[(size_t)MTOT * C3];           // 100 MB (fp16)
__device__ __half g_xh[(size_t)MTOT * Ct];
__device__ __half g_wqh[(size_t)C3 * Ct];             // transposed [N][K]
__device__ __half g_wql[(size_t)C3 * Ct];
__device__ __half g_wph[(size_t)Ct * Ct];             // transposed [N][K]
__device__ __half g_wpl[(size_t)Ct * Ct];
__device__ __half g_y[(size_t)MTOT * Ct];

DEVINLINE void mma16f(float* d, const uint32_t* a, const uint32_t* b) {
    asm volatile(
        "mma.sync.aligned.m16n8k16.row.col.f32.f16.f16.f32 "
        "{%0,%1,%2,%3}, {%4,%5,%6,%7}, {%8,%9}, {%0,%1,%2,%3};"
        : "+f"(d[0]), "+f"(d[1]), "+f"(d[2]), "+f"(d[3])
        : "r"(a[0]), "r"(a[1]), "r"(a[2]), "r"(a[3]), "r"(b[0]), "r"(b[1]));
}

DEVINLINE void ldsm_x4(uint32_t& r0, uint32_t& r1, uint32_t& r2, uint32_t& r3,
                       uint32_t addr) {
    asm volatile("ldmatrix.sync.aligned.m8n8.x4.shared.b16 {%0,%1,%2,%3}, [%4];"
                 : "=r"(r0), "=r"(r1), "=r"(r2), "=r"(r3) : "r"(addr));
}

DEVINLINE void ldsm_x4_t(uint32_t& r0, uint32_t& r1, uint32_t& r2, uint32_t& r3,
                         uint32_t addr) {
    asm volatile("ldmatrix.sync.aligned.m8n8.x4.trans.shared.b16 {%0,%1,%2,%3}, [%4];"
                 : "=r"(r0), "=r"(r1), "=r"(r2), "=r"(r3) : "r"(addr));
}

DEVINLINE void cpasync16(uint32_t saddr, const void* g) {
    asm volatile("cp.async.cg.shared.global [%0], [%1], 16;\n"
                 :: "r"(saddr), "l"(g));
}
DEVINLINE void cp_commit() { asm volatile("cp.async.commit_group;\n"); }
DEVINLINE void cp_wait0()  { asm volatile("cp.async.wait_group 0;\n" ::: "memory"); }

DEVINLINE uint32_t packh2(float x, float y) {
    __half2 h = __floats2half2_rn(x, y);
    return *(uint32_t*)&h;
}

DEVINLINE float fexp2(float x) {
    float y;
    asm("ex2.approx.f32 %0, %1;" : "=f"(y) : "f"(x));
    return y;
}

// ---------------------------------------------------------------------------
// Pre-pass kernels
// ---------------------------------------------------------------------------
__global__ void tohalf_kernel(const float* __restrict__ src,
                              __half* __restrict__ dst, size_t n)
{
    size_t i = (size_t)blockIdx.x * blockDim.x + threadIdx.x;
    if (i < n) dst[i] = __float2half(src[i]);
}

// W[K][N] fp32 -> (hi, lo) fp16, transposed to [N][K]
__global__ void split_transpose_kernel(const float* __restrict__ W,
                                       __half* __restrict__ th,
                                       __half* __restrict__ tl,
                                       int K, int N)
{
    __shared__ float tile[32][33];
    int nx = blockIdx.x * 32, ky = blockIdx.y * 32;
    int tx = threadIdx.x, ty = threadIdx.y;   // 32 x 8
#pragma unroll
    for (int s = 0; s < 4; ++s)
        tile[ty + 8 * s][tx] = W[(size_t)(ky + ty + 8 * s) * N + nx + tx];
    __syncthreads();
#pragma unroll
    for (int s = 0; s < 4; ++s) {
        float v = tile[tx][ty + 8 * s];
        __half h = __float2half(v);
        __half l = __float2half(v - __half2float(h));
        size_t idx = (size_t)(nx + ty + 8 * s) * K + ky + tx;
        th[idx] = h; tl[idx] = l;
    }
}

// ---------------------------------------------------------------------------
// fp16 split GEMM: C[M,N] = A[M,K] @ (Bh[+Bl])^T  (B arrays are [N][K]).
// CTA tile 128x128, 8 warps (2x4), warp tile 64x32, K-tile 64, 2-stage,
// single sync per tile, 2 CTAs/SM (4 warps/SMSP).
// lo pass only where use_lo (q,k of GEMM1).
// ropep: fused RoPE + fp16 out (qkv path); else fp32 out.
// ---------------------------------------------------------------------------
static constexpr int GAST = 36;                      // u32 row stride (32 data + 4)
static constexpr int GROWB = GAST * 4;               // 144 B row stride
static constexpr int GA_U32 = 128 * GAST;            // 4608 (A tile)
static constexpr int GB_U32 = 128 * GAST;            // 4608 (per B array)
static constexpr int GSTG_U32 = GA_U32 + 2 * GB_U32; // 13824 per stage
static constexpr int GEMM_SMEM = 2 * GSTG_U32 * 4;   // 110592 B -> 2 CTAs/SM

__global__ __launch_bounds__(256, 2) void gemm_fp16x2(
    const __half* __restrict__ Ah,
    const __half* __restrict__ Bh, const __half* __restrict__ Bl,
    void* __restrict__ Cout, int M, int N, int K,
    const float* __restrict__ ropep)
{
    extern __shared__ uint32_t sm[];

    const int tid = threadIdx.x;
    const int w = tid >> 5, lane = tid & 31;
    const int wm = w >> 2, wn = w & 3;          // 2 x 4 warps, 64x32 each
    const int g = lane >> 2, tg = lane & 3;
    const int m0 = blockIdx.y * 128, n0 = blockIdx.x * 128;

    // lo correction pass only for q,k columns of the qkv GEMM.
    const bool use_lo = (ropep != nullptr) && (n0 < 2 * Ct);

    const uint32_t sbase = (uint32_t)__cvta_generic_to_shared(sm);

    // per-lane ldmatrix base offsets (bytes)
    const uint32_t a_loff =
        (uint32_t)(wm * 64 + (lane & 15)) * GROWB + ((lane >> 4) & 1) * 16;
    const uint32_t b_loff =
        (uint32_t)(wn * 32 + ((lane >> 4) & 1) * 8 + (lane & 7)) * GROWB +
        ((lane >> 3) & 1) * 16;

    auto issue_stage = [&](int kt, int s) {
        const uint32_t st = sbase + (uint32_t)s * GSTG_U32 * 4;
        const uint32_t stA  = st;
        const uint32_t stBh = st + GA_U32 * 4;
        const uint32_t stBl = st + GA_U32 * 4 + GB_U32 * 4;
#pragma unroll
        for (int i = 0; i < 4; ++i) {            // A: 1024 16B-chunks / 256 thr
            int id = tid + i * 256;
            int r = id >> 3, c = id & 7;
            uint32_t d = (uint32_t)r * GROWB + c * 16;
            cpasync16(stA + d, Ah + (size_t)(m0 + r) * K + kt + c * 8);
        }
#pragma unroll
        for (int i = 0; i < 4; ++i) {            // B: 1024 16B-chunks (+lo)
            int id = tid + i * 256;
            int r = id >> 3, c = id & 7;
            uint32_t d = (uint32_t)r * GROWB + c * 16;
            size_t gb = (size_t)(n0 + r) * K + kt + c * 8;
            cpasync16(stBh + d, Bh + gb);
            if (use_lo) cpasync16(stBl + d, Bl + gb);
        }
    };

    float acc[4][4][4];
#pragma unroll
    for (int mt = 0; mt < 4; ++mt)
#pragma unroll
        for (int nt = 0; nt < 4; ++nt)
#pragma unroll
            for (int q = 0; q < 4; ++q) acc[mt][nt][q] = 0.f;

    const int ntiles = K / 64;
    issue_stage(0, 0); cp_commit();
    cp_wait0();
    __syncthreads();

    for (int t = 0; t < ntiles; ++t) {
        // issue next tile into the other buffer (fully consumed last iter)
        if (t + 1 < ntiles) issue_stage((t + 1) * 64, (t + 1) & 1);
        cp_commit();

        const uint32_t stb = sbase + (uint32_t)(t & 1) * GSTG_U32 * 4;
        const uint32_t aA  = stb + a_loff;
        const uint32_t aBh = stb + GA_U32 * 4 + b_loff;
        const uint32_t aBl = aBh + GB_U32 * 4;

#pragma unroll
        for (int ks = 0; ks < 4; ++ks) {
            const uint32_t kob = (uint32_t)ks * 32;   // 8 u32 = 32 B per step
            uint32_t av[4][4], bh[4][2], bl[4][2];
#pragma unroll
            for (int mt = 0; mt < 4; ++mt)
                ldsm_x4(av[mt][0], av[mt][1], av[mt][2], av[mt][3],
                        aA + (uint32_t)mt * (16 * GROWB) + kob);
#pragma unroll
            for (int p = 0; p < 2; ++p)
                ldsm_x4(bh[2 * p][0], bh[2 * p][1], bh[2 * p + 1][0], bh[2 * p + 1][1],
                        aBh + (uint32_t)p * (16 * GROWB) + kob);
            if (use_lo) {
#pragma unroll
                for (int p = 0; p < 2; ++p)
                    ldsm_x4(bl[2 * p][0], bl[2 * p][1], bl[2 * p + 1][0], bl[2 * p + 1][1],
                            aBl + (uint32_t)p * (16 * GROWB) + kob);
            }
#pragma unroll
            for (int mt = 0; mt < 4; ++mt)
#pragma unroll
                for (int nt = 0; nt < 4; ++nt)
                    mma16f(acc[mt][nt], av[mt], bh[nt]);   // hi*hi
            if (use_lo) {
#pragma unroll
                for (int mt = 0; mt < 4; ++mt)
#pragma unroll
                    for (int nt = 0; nt < 4; ++nt)
                        mma16f(acc[mt][nt], av[mt], bl[nt]);   // hi*lo
            }
        }

        cp_wait0();          // next tile landed (overlapped with compute above)
        __syncthreads();     // single barrier per tile
    }

    if (ropep != nullptr) {
        // qkv path: RoPE on q,k columns, fp16 output
        __half* Cm = (__half*)Cout;
#pragma unroll
        for (int mt = 0; mt < 4; ++mt)
#pragma unroll
            for (int nt = 0; nt < 4; ++nt) {
                int r = m0 + wm * 64 + mt * 16 + g;
                int c = n0 + wn * 32 + nt * 8 + tg * 2;
                float2 v0 = make_float2(acc[mt][nt][0], acc[mt][nt][1]);
                float2 v1 = make_float2(acc[mt][nt][2], acc[mt][nt][3]);
                if (c < 2 * Ct) {
                    int d = (c & (HDt - 1)) >> 1;
                    float2 cs0 = *(const float2*)(ropep + (size_t)((r & (Tt - 1)) * 64 + d) * 2);
                    float2 cs1 = *(const float2*)(ropep + (size_t)(((r + 8) & (Tt - 1)) * 64 + d) * 2);
                    v0 = make_float2(v0.x * cs0.x - v0.y * cs0.y,
                                     v0.y * cs0.x + v0.x * cs0.y);
                    v1 = make_float2(v1.x * cs1.x - v1.y * cs1.y,
                                     v1.y * cs1.x + v1.x * cs1.y);
                }
                *(uint32_t*)(Cm + (size_t)r * N + c) = packh2(v0.x, v0.y);
                *(uint32_t*)(Cm + (size_t)(r + 8) * N + c) = packh2(v1.x, v1.y);
            }
    } else {
        float* Cm = (float*)Cout;
#pragma unroll
        for (int mt = 0; mt < 4; ++mt)
#pragma unroll
            for (int nt = 0; nt < 4; ++nt) {
                int r = m0 + wm * 64 + mt * 16 + g;
                int c = n0 + wn * 32 + nt * 8 + tg * 2;
                *(float2*)(Cm + (size_t)r * N + c) =
                    make_float2(acc[mt][nt][0], acc[mt][nt][1]);
                *(float2*)(Cm + (size_t)(r + 8) * N + c) =
                    make_float2(acc[mt][nt][2], acc[mt][nt][3]);
            }
    }
}

// ---------------------------------------------------------------------------
// Flash attention, fp16 m16n8k16, causal. 1 block = (b, h, 128 q rows),
// 256 thr (8 warps x 16 rows). kv tile 64, 2-buffer cp.async,
// single sync per kv tile. exp2-domain softmax. V via ldmatrix.x4.trans.
// ---------------------------------------------------------------------------
static constexpr int KVST = 68;                       // u32 row stride
static constexpr int KROWB = KVST * 4;                // 272 B
static constexpr int KV_U32 = 64 * KVST;              // per K or V tile
static constexpr int KVSTG = 2 * KV_U32;              // K+V per stage
static constexpr int FLASH_SMEM = 2 * KVSTG * 4;      // 69632 B

__global__ __launch_bounds__(256, 1) void flash_kernel(
    const __half* __restrict__ qkv, __half* __restrict__ y)
{
    extern __shared__ uint32_t sm[];
    const uint32_t sbase = (uint32_t)__cvta_generic_to_shared(sm);

    const int tid = threadIdx.x;
    const int w = tid >> 5, lane = tid & 31;
    const int g = lane >> 2, tg = lane & 3;
    const int qt = (int)gridDim.x - 1 - (int)blockIdx.x;   // heavy tiles first
    const int bh = blockIdx.y;
    const int b = bh >> 4, h = bh & 15;
    const int q0 = qt * 128;
    const __half* base = qkv + (size_t)(b * Tt) * C3;
    const int qcol = h * HDt, kcol = Ct + h * HDt;
    const int wr0 = w * 16;
    // scale * log2(e): softmax tracked in exp2 domain
    const float scale2 = 0.0883883476483184f * 1.4426950408889634f;

    // per-lane ldmatrix.x4 offset for K fragments (nt-pair layout)
    const uint32_t k_loff =
        (uint32_t)(((lane >> 4) & 1) * 8 + (lane & 7)) * KROWB +
        ((lane >> 3) & 1) * 16;
    // per-lane ldmatrix.x4.trans offset for V (nt-pair per x4)
    const uint32_t v_loff =
        (uint32_t)(lane & 15) * KROWB + ((lane >> 4) & 1) * 16;

    // ---- Stage Q (two 64-row passes through buf1's K region), frags to regs
    uint32_t qf[8][4];
    {
        const uint32_t qstage = sbase + KVSTG * 4;    // buf1 K area
        uint32_t* Qs = sm + KVSTG;
#pragma unroll
        for (int pass = 0; pass < 2; ++pass) {
#pragma unroll
            for (int i = 0; i < 4; ++i) {
                int id = tid + i * 256;
                int r = id >> 4, c = id & 15;
                cpasync16(qstage + (uint32_t)r * KROWB + c * 16,
                          base + (size_t)(q0 + pass * 64 + r) * C3 + qcol + c * 8);
            }
            cp_commit(); cp_wait0();
            __syncthreads();
            if ((w >> 2) == pass) {
                int rl = (wr0 & 63) + g;
#pragma unroll
                for (int kk = 0; kk < 8; ++kk) {
                    int a0 = rl * KVST + kk * 8 + tg;
                    int a1 = (rl + 8) * KVST + kk * 8 + tg;
                    qf[kk][0] = Qs[a0];
                    qf[kk][1] = Qs[a1];
                    qf[kk][2] = Qs[a0 + 4];
                    qf[kk][3] = Qs[a1 + 4];
                }
            }
            __syncthreads();
        }
    }

    auto issue_kv = [&](int j, int s) {
        const uint32_t stK = sbase + (uint32_t)s * KVSTG * 4;
        const uint32_t stV = stK + KV_U32 * 4;
        const int kv0 = j * 64;
#pragma unroll
        for (int i = 0; i < 4; ++i) {
            int id = tid + i * 256;
            int r = id >> 4, c = id & 15;
            uint32_t d = (uint32_t)r * KROWB + c * 16;
            const __half* kp = base + (size_t)(kv0 + r) * C3 + kcol + c * 8;
            cpasync16(stK + d, kp);
            cpasync16(stV + d, kp + Ct);
        }
    };

    float m_a = -1e30f, m_b = -1e30f, l_a = 0.f, l_b = 0.f;
    float o[16][4];
#pragma unroll
    for (int nt = 0; nt < 16; ++nt)
#pragma unroll
        for (int q = 0; q < 4; ++q) o[nt][q] = 0.f;

    const int njt = 2 * qt + 2;
    issue_kv(0, 0); cp_commit();
    cp_wait0();
    __syncthreads();

    for (int j = 0; j < njt; ++j) {
        if (j + 1 < njt) issue_kv(j + 1, (j + 1) & 1);
        cp_commit();

        const int kv0 = j * 64;
        const uint32_t kbyte = sbase + (j & 1) * KVSTG * 4;
        const uint32_t vbyte = kbyte + KV_U32 * 4;
        const uint32_t aK = kbyte + k_loff;
        const uint32_t aV = vbyte + v_loff;

        if (kv0 <= q0 + wr0 + 15) {          // warp-level causal skip
            float s[8][4];
#pragma unroll
            for (int nt = 0; nt < 8; ++nt)
#pragma unroll
                for (int q = 0; q < 4; ++q) s[nt][q] = 0.f;
            // S = Q @ K^T : 8 k-chunks x 4 nt-pairs (ldmatrix.x4 each)
#pragma unroll
            for (int kk = 0; kk < 8; ++kk) {
#pragma unroll
                for (int p = 0; p < 4; ++p) {
                    uint32_t b0[2], b1[2];
                    ldsm_x4(b0[0], b0[1], b1[0], b1[1],
                            aK + (uint32_t)p * (16 * KROWB) + kk * 32);
                    mma16f(s[2 * p],     qf[kk], b0);
                    mma16f(s[2 * p + 1], qf[kk], b1);
                }
            }

            // scale into exp2 domain
#pragma unroll
            for (int nt = 0; nt < 8; ++nt)
#pragma unroll
                for (int q = 0; q < 4; ++q) s[nt][q] *= scale2;

            if (kv0 + 63 > q0 + wr0) {       // diagonal tile: mask
                int ra = q0 + wr0 + g, rb = ra + 8;
#pragma unroll
                for (int nt = 0; nt < 8; ++nt) {
                    int c0 = kv0 + nt * 8 + tg * 2;
                    if (c0     > ra) s[nt][0] = -1e30f;
                    if (c0 + 1 > ra) s[nt][1] = -1e30f;
                    if (c0     > rb) s[nt][2] = -1e30f;
                    if (c0 + 1 > rb) s[nt][3] = -1e30f;
                }
            }

            // online softmax (exp2 domain)
            float tma = -1e30f, tmb = -1e30f;
#pragma unroll
            for (int nt = 0; nt < 8; ++nt) {
                tma = fmaxf(tma, fmaxf(s[nt][0], s[nt][1]));
                tmb = fmaxf(tmb, fmaxf(s[nt][2], s[nt][3]));
            }
            tma = fmaxf(tma, __shfl_xor_sync(0xffffffffu, tma, 1));
            tma = fmaxf(tma, __shfl_xor_sync(0xffffffffu, tma, 2));
            tmb = fmaxf(tmb, __shfl_xor_sync(0xffffffffu, tmb, 1));
            tmb = fmaxf(tmb, __shfl_xor_sync(0xffffffffu, tmb, 2));
            float mna = fmaxf(m_a, tma), mnb = fmaxf(m_b, tmb);
            float aa = fexp2(m_a - mna), ab = fexp2(m_b - mnb);
            float rsa = 0.f, rsb = 0.f;
#pragma unroll
            for (int nt = 0; nt < 8; ++nt) {
                s[nt][0] = fexp2(s[nt][0] - mna);
                s[nt][1] = fexp2(s[nt][1] - mna);
                s[nt][2] = fexp2(s[nt][2] - mnb);
                s[nt][3] = fexp2(s[nt][3] - mnb);
                rsa += s[nt][0] + s[nt][1];
                rsb += s[nt][2] + s[nt][3];
            }
            rsa += __shfl_xor_sync(0xffffffffu, rsa, 1);
            rsa += __shfl_xor_sync(0xffffffffu, rsa, 2);
            rsb += __shfl_xor_sync(0xffffffffu, rsb, 1);
            rsb += __shfl_xor_sync(0xffffffffu, rsb, 2);
            l_a = l_a * aa + rsa;
            l_b = l_b * ab + rsb;
            m_a = mna;
            m_b = mnb;
#pragma unroll
            for (int nt = 0; nt < 16; ++nt) {
                o[nt][0] *= aa; o[nt][1] *= aa;
                o[nt][2] *= ab; o[nt][3] *= ab;
            }

            // O += P @ V : P repacked in registers, V via ldmatrix.x4.trans
#pragma unroll
            for (int kk = 0; kk < 4; ++kk) {
                uint32_t pa[4];
                pa[0] = packh2(s[2 * kk][0],     s[2 * kk][1]);
                pa[1] = packh2(s[2 * kk][2],     s[2 * kk][3]);
                pa[2] = packh2(s[2 * kk + 1][0], s[2 * kk + 1][1]);
                pa[3] = packh2(s[2 * kk + 1][2], s[2 * kk + 1][3]);
                uint32_t vrow = aV + (uint32_t)(kk * 16) * KROWB;
#pragma unroll
                for (int p = 0; p < 8; ++p) {
                    uint32_t b0[2], b1[2];
                    ldsm_x4_t(b0[0], b0[1], b1[0], b1[1], vrow + p * 32);
                    mma16f(o[2 * p],     pa, b0);
                    mma16f(o[2 * p + 1], pa, b1);
                }
            }
        }

        cp_wait0();          // tile j+1 landed (overlapped with compute)
        __syncthreads();     // single barrier per kv tile
    }

    // epilogue: normalize, fp16 y
    float inva = 1.f / l_a, invb = 1.f / l_b;
    int rt = b * Tt + q0 + wr0 + g;
#pragma unroll
    for (int nt = 0; nt < 16; ++nt) {
        int c = h * HDt + nt * 8 + tg * 2;
        *(uint32_t*)(y + (size_t)rt * Ct + c) =
            packh2(o[nt][0] * inva, o[nt][1] * inva);
        *(uint32_t*)(y + (size_t)(rt + 8) * Ct + c) =
            packh2(o[nt][2] * invb, o[nt][3] * invb);
    }
}

// ---------------------------------------------------------------------------
extern "C" void kernel_launch(void* const* d_in, const int* in_sizes, int n_in,
                              void* d_out, int out_size)
{
    const float* x     = (const float*)d_in[0];
    const float* rope  = (const float*)d_in[1];
    const float* Wqkv  = (const float*)d_in[2];
    const float* Wproj = (const float*)d_in[3];
    float* out = (float*)d_out;

    __half *qkv, *xh, *wqh, *wql, *wph, *wpl, *y;
    cudaGetSymbolAddress((void**)&qkv, g_qkv);
    cudaGetSymbolAddress((void**)&xh, g_xh);
    cudaGetSymbolAddress((void**)&wqh, g_wqh);
    cudaGetSymbolAddress((void**)&wql, g_wql);
    cudaGetSymbolAddress((void**)&wph, g_wph);
    cudaGetSymbolAddress((void**)&wpl, g_wpl);
    cudaGetSymbolAddress((void**)&y, g_y);

    cudaFuncSetAttribute(gemm_fp16x2, cudaFuncAttributeMaxDynamicSharedMemorySize,
                         GEMM_SMEM);
    cudaFuncSetAttribute(flash_kernel, cudaFuncAttributeMaxDynamicSharedMemorySize,
                         FLASH_SMEM);

    // 0) pre-pass: x -> fp16 ; W -> fp16 hi/lo transposed
    {
        size_t nx = (size_t)MTOT * Ct;
        tohalf_kernel<<<(unsigned)((nx + 255) / 256), 256>>>(x, xh, nx);
        split_transpose_kernel<<<dim3(C3 / 32, Ct / 32), dim3(32, 8)>>>(Wqkv, wqh, wql, Ct, C3);
        split_transpose_kernel<<<dim3(Ct / 32, Ct / 32), dim3(32, 8)>>>(Wproj, wph, wpl, Ct, Ct);
    }

    // 1) qkv = x @ Wqkv + fused RoPE, fp16 out  (M=8192, N=6144, K=2048)
    //    (lo pass active only for q,k column CTAs)
    gemm_fp16x2<<<dim3(C3 / 128, MTOT / 128), 256, GEMM_SMEM>>>(
        xh, wqh, wql, qkv, MTOT, C3, Ct, rope);

    // 2) flash attention -> y (fp16)
    flash_kernel<<<dim3(Tt / 128, Bt * Ht), 256, FLASH_SMEM>>>(qkv, y);

    // 3) out = y @ Wproj, fp32 out, single-pass  (M=8192, N=2048, K=2048)
    gemm_fp16x2<<<dim3(Ct / 128, MTOT / 128), 256, GEMM_SMEM>>>(
        y, wph, wpl, out, MTOT, Ct, Ct, nullptr);
}

// round 16
// speedup vs baseline: 1.0399x; 1.0399x over previous
#include <cuda_runtime.h>
#include <cuda_fp16.h>
#include <cstdint>

// ---------------------------------------------------------------------------
// CasualSelfAttention: B=4, T=2048, C=2048, H=16, HD=128
//   qkv = x @ Wqkv (+fused RoPE, fp16 out) ; flash-attn (fp16 mma, causal) ;
//   out = y @ Wproj
// GEMMs: fp16 split GEMM (W-lo pass only on q,k columns of GEMM1).
//        CTA tile 128x128, 4 warps (2x2 of 64x64), 2 CTAs/SM  [round-14 cfg].
// Flash: fp16 m16n8k16, 64 q-rows/CTA, 4 warps, 2 CTAs/SM co-resident,
//        P in registers, K via ldmatrix.x4, V via ldmatrix.x4.trans,
//        exp2-domain softmax, single sync per kv tile.
// ---------------------------------------------------------------------------

#define DEVINLINE __device__ __forceinline__

static constexpr int Bt = 4;
static constexpr int Tt = 2048;
static constexpr int Ct = 2048;
static constexpr int Ht = 16;
static constexpr int HDt = 128;
static constexpr int MTOT = Bt * Tt;        // 8192
static constexpr int C3 = 3 * Ct;           // 6144

// Scratch (device globals: allocation-free rule)
__device__ __half g_qkv[(size_t)MTOT * C3];           // 100 MB (fp16)
__device__ __half g_xh[(size_t)MTOT * Ct];
__device__ __half g_wqh[(size_t)C3 * Ct];             // transposed [N][K]
__device__ __half g_wql[(size_t)C3 * Ct];
__device__ __half g_wph[(size_t)Ct * Ct];             // transposed [N][K]
__device__ __half g_wpl[(size_t)Ct * Ct];
__device__ __half g_y[(size_t)MTOT * Ct];

DEVINLINE void mma16f(float* d, const uint32_t* a, const uint32_t* b) {
    asm volatile(
        "mma.sync.aligned.m16n8k16.row.col.f32.f16.f16.f32 "
        "{%0,%1,%2,%3}, {%4,%5,%6,%7}, {%8,%9}, {%0,%1,%2,%3};"
        : "+f"(d[0]), "+f"(d[1]), "+f"(d[2]), "+f"(d[3])
        : "r"(a[0]), "r"(a[1]), "r"(a[2]), "r"(a[3]), "r"(b[0]), "r"(b[1]));
}

DEVINLINE void ldsm_x4(uint32_t& r0, uint32_t& r1, uint32_t& r2, uint32_t& r3,
                       uint32_t addr) {
    asm volatile("ldmatrix.sync.aligned.m8n8.x4.shared.b16 {%0,%1,%2,%3}, [%4];"
                 : "=r"(r0), "=r"(r1), "=r"(r2), "=r"(r3) : "r"(addr));
}

DEVINLINE void ldsm_x4_t(uint32_t& r0, uint32_t& r1, uint32_t& r2, uint32_t& r3,
                         uint32_t addr) {
    asm volatile("ldmatrix.sync.aligned.m8n8.x4.trans.shared.b16 {%0,%1,%2,%3}, [%4];"
                 : "=r"(r0), "=r"(r1), "=r"(r2), "=r"(r3) : "r"(addr));
}

DEVINLINE void cpasync16(uint32_t saddr, const void* g) {
    asm volatile("cp.async.cg.shared.global [%0], [%1], 16;\n"
                 :: "r"(saddr), "l"(g));
}
DEVINLINE void cp_commit() { asm volatile("cp.async.commit_group;\n"); }
DEVINLINE void cp_wait0()  { asm volatile("cp.async.wait_group 0;\n" ::: "memory"); }

DEVINLINE uint32_t packh2(float x, float y) {
    __half2 h = __floats2half2_rn(x, y);
    return *(uint32_t*)&h;
}

DEVINLINE float fexp2(float x) {
    float y;
    asm("ex2.approx.f32 %0, %1;" : "=f"(y) : "f"(x));
    return y;
}

// ---------------------------------------------------------------------------
// Pre-pass kernels
// ---------------------------------------------------------------------------
__global__ void tohalf_kernel(const float* __restrict__ src,
                              __half* __restrict__ dst, size_t n)
{
    size_t i = (size_t)blockIdx.x * blockDim.x + threadIdx.x;
    if (i < n) dst[i] = __float2half(src[i]);
}

// W[K][N] fp32 -> (hi, lo) fp16, transposed to [N][K]
__global__ void split_transpose_kernel(const float* __restrict__ W,
                                       __half* __restrict__ th,
                                       __half* __restrict__ tl,
                                       int K, int N)
{
    __shared__ float tile[32][33];
    int nx = blockIdx.x * 32, ky = blockIdx.y * 32;
    int tx = threadIdx.x, ty = threadIdx.y;   // 32 x 8
#pragma unroll
    for (int s = 0; s < 4; ++s)
        tile[ty + 8 * s][tx] = W[(size_t)(ky + ty + 8 * s) * N + nx + tx];
    __syncthreads();
#pragma unroll
    for (int s = 0; s < 4; ++s) {
        float v = tile[tx][ty + 8 * s];
        __half h = __float2half(v);
        __half l = __float2half(v - __half2float(h));
        size_t idx = (size_t)(nx + ty + 8 * s) * K + ky + tx;
        th[idx] = h; tl[idx] = l;
    }
}

// ---------------------------------------------------------------------------
// fp16 split GEMM: C[M,N] = A[M,K] @ (Bh[+Bl])^T  (B arrays are [N][K]).
// CTA tile 128x128, 4 warps (2x2), warp tile 64x64, K-tile 64, 2-stage,
// single sync per tile, 2 CTAs/SM. lo pass only where use_lo (q,k of GEMM1).
// ropep: fused RoPE + fp16 out (qkv path); else fp32 out.   [round-14 config]
// ---------------------------------------------------------------------------
static constexpr int GAST = 36;                      // u32 row stride (32 data + 4)
static constexpr int GROWB = GAST * 4;               // 144 B row stride
static constexpr int GA_U32 = 128 * GAST;            // 4608 (A tile)
static constexpr int GB_U32 = 128 * GAST;            // 4608 (per B array)
static constexpr int GSTG_U32 = GA_U32 + 2 * GB_U32; // 13824 per stage
static constexpr int GEMM_SMEM = 2 * GSTG_U32 * 4;   // 110592 B -> 2 CTAs/SM

__global__ __launch_bounds__(128, 2) void gemm_fp16x2(
    const __half* __restrict__ Ah,
    const __half* __restrict__ Bh, const __half* __restrict__ Bl,
    void* __restrict__ Cout, int M, int N, int K,
    const float* __restrict__ ropep)
{
    extern __shared__ uint32_t sm[];

    const int tid = threadIdx.x;
    const int w = tid >> 5, lane = tid & 31;
    const int wm = w >> 1, wn = w & 1;          // 2 x 2 warps, 64x64 each
    const int g = lane >> 2, tg = lane & 3;
    const int m0 = blockIdx.y * 128, n0 = blockIdx.x * 128;

    // lo correction pass only for q,k columns of the qkv GEMM.
    const bool use_lo = (ropep != nullptr) && (n0 < 2 * Ct);

    const uint32_t sbase = (uint32_t)__cvta_generic_to_shared(sm);

    // per-lane ldmatrix base offsets (bytes)
    const uint32_t a_loff =
        (uint32_t)(wm * 64 + (lane & 15)) * GROWB + ((lane >> 4) & 1) * 16;
    const uint32_t b_loff =
        (uint32_t)(wn * 64 + ((lane >> 4) & 1) * 8 + (lane & 7)) * GROWB +
        ((lane >> 3) & 1) * 16;

    auto issue_stage = [&](int kt, int s) {
        const uint32_t st = sbase + (uint32_t)s * GSTG_U32 * 4;
        const uint32_t stA  = st;
        const uint32_t stBh = st + GA_U32 * 4;
        const uint32_t stBl = st + GA_U32 * 4 + GB_U32 * 4;
#pragma unroll
        for (int i = 0; i < 8; ++i) {            // A: 1024 16B-chunks / 128 thr
            int id = tid + i * 128;
            int r = id >> 3, c = id & 7;
            uint32_t d = (uint32_t)r * GROWB + c * 16;
            cpasync16(stA + d, Ah + (size_t)(m0 + r) * K + kt + c * 8);
        }
#pragma unroll
        for (int i = 0; i < 8; ++i) {            // B: 1024 16B-chunks (+lo)
            int id = tid + i * 128;
            int r = id >> 3, c = id & 7;
            uint32_t d = (uint32_t)r * GROWB + c * 16;
            size_t gb = (size_t)(n0 + r) * K + kt + c * 8;
            cpasync16(stBh + d, Bh + gb);
            if (use_lo) cpasync16(stBl + d, Bl + gb);
        }
    };

    float acc[4][8][4];
#pragma unroll
    for (int mt = 0; mt < 4; ++mt)
#pragma unroll
        for (int nt = 0; nt < 8; ++nt)
#pragma unroll
            for (int q = 0; q < 4; ++q) acc[mt][nt][q] = 0.f;

    const int ntiles = K / 64;
    issue_stage(0, 0); cp_commit();
    cp_wait0();
    __syncthreads();

    for (int t = 0; t < ntiles; ++t) {
        // issue next tile into the other buffer (fully consumed last iter)
        if (t + 1 < ntiles) issue_stage((t + 1) * 64, (t + 1) & 1);
        cp_commit();

        const uint32_t stb = sbase + (uint32_t)(t & 1) * GSTG_U32 * 4;
        const uint32_t aA  = stb + a_loff;
        const uint32_t aBh = stb + GA_U32 * 4 + b_loff;
        const uint32_t aBl = aBh + GB_U32 * 4;

#pragma unroll
        for (int ks = 0; ks < 4; ++ks) {
            const uint32_t kob = (uint32_t)ks * 32;   // 8 u32 = 32 B per step
            uint32_t av[4][4], bh[8][2], bl[8][2];
#pragma unroll
            for (int mt = 0; mt < 4; ++mt)
                ldsm_x4(av[mt][0], av[mt][1], av[mt][2], av[mt][3],
                        aA + (uint32_t)mt * (16 * GROWB) + kob);
#pragma unroll
            for (int p = 0; p < 4; ++p)
                ldsm_x4(bh[2 * p][0], bh[2 * p][1], bh[2 * p + 1][0], bh[2 * p + 1][1],
                        aBh + (uint32_t)p * (16 * GROWB) + kob);
            if (use_lo) {
#pragma unroll
                for (int p = 0; p < 4; ++p)
                    ldsm_x4(bl[2 * p][0], bl[2 * p][1], bl[2 * p + 1][0], bl[2 * p + 1][1],
                            aBl + (uint32_t)p * (16 * GROWB) + kob);
            }
#pragma unroll
            for (int mt = 0; mt < 4; ++mt)
#pragma unroll
                for (int nt = 0; nt < 8; ++nt)
                    mma16f(acc[mt][nt], av[mt], bh[nt]);   // hi*hi
            if (use_lo) {
#pragma unroll
                for (int mt = 0; mt < 4; ++mt)
#pragma unroll
                    for (int nt = 0; nt < 8; ++nt)
                        mma16f(acc[mt][nt], av[mt], bl[nt]);   // hi*lo
            }
        }

        cp_wait0();          // next tile landed (overlapped with compute above)
        __syncthreads();     // single barrier per tile (4 warps only)
    }

    if (ropep != nullptr) {
        // qkv path: RoPE on q,k columns, fp16 output
        __half* Cm = (__half*)Cout;
#pragma unroll
        for (int mt = 0; mt < 4; ++mt)
#pragma unroll
            for (int nt = 0; nt < 8; ++nt) {
                int r = m0 + wm * 64 + mt * 16 + g;
                int c = n0 + wn * 64 + nt * 8 + tg * 2;
                float2 v0 = make_float2(acc[mt][nt][0], acc[mt][nt][1]);
                float2 v1 = make_float2(acc[mt][nt][2], acc[mt][nt][3]);
                if (c < 2 * Ct) {
                    int d = (c & (HDt - 1)) >> 1;
                    float2 cs0 = *(const float2*)(ropep + (size_t)((r & (Tt - 1)) * 64 + d) * 2);
                    float2 cs1 = *(const float2*)(ropep + (size_t)(((r + 8) & (Tt - 1)) * 64 + d) * 2);
                    v0 = make_float2(v0.x * cs0.x - v0.y * cs0.y,
                                     v0.y * cs0.x + v0.x * cs0.y);
                    v1 = make_float2(v1.x * cs1.x - v1.y * cs1.y,
                                     v1.y * cs1.x + v1.x * cs1.y);
                }
                *(uint32_t*)(Cm + (size_t)r * N + c) = packh2(v0.x, v0.y);
                *(uint32_t*)(Cm + (size_t)(r + 8) * N + c) = packh2(v1.x, v1.y);
            }
    } else {
        float* Cm = (float*)Cout;
#pragma unroll
        for (int mt = 0; mt < 4; ++mt)
#pragma unroll
            for (int nt = 0; nt < 8; ++nt) {
                int r = m0 + wm * 64 + mt * 16 + g;
                int c = n0 + wn * 64 + nt * 8 + tg * 2;
                *(float2*)(Cm + (size_t)r * N + c) =
                    make_float2(acc[mt][nt][0], acc[mt][nt][1]);
                *(float2*)(Cm + (size_t)(r + 8) * N + c) =
                    make_float2(acc[mt][nt][2], acc[mt][nt][3]);
            }
    }
}

// ---------------------------------------------------------------------------
// Flash attention, fp16 m16n8k16, causal. 1 block = (b, h, 64 q rows),
// 128 thr (4 warps x 16 rows), 2 CTAs/SM. kv tile 64, 2-buffer cp.async,
// single sync per kv tile. exp2-domain softmax. V via ldmatrix.x4.trans.
// Per-warp instruction stream identical to the 128-row version.
// ---------------------------------------------------------------------------
static constexpr int KVST = 68;                       // u32 row stride
static constexpr int KROWB = KVST * 4;                // 272 B
static constexpr int KV_U32 = 64 * KVST;              // per K or V tile
static constexpr int KVSTG = 2 * KV_U32;              // K+V per stage
static constexpr int FLASH_SMEM = 2 * KVSTG * 4;      // 69632 B -> 2 CTAs/SM

__global__ __launch_bounds__(128, 2) void flash_kernel(
    const __half* __restrict__ qkv, __half* __restrict__ y)
{
    extern __shared__ uint32_t sm[];
    const uint32_t sbase = (uint32_t)__cvta_generic_to_shared(sm);

    const int tid = threadIdx.x;
    const int w = tid >> 5, lane = tid & 31;
    const int g = lane >> 2, tg = lane & 3;
    const int qt = (int)gridDim.x - 1 - (int)blockIdx.x;   // heavy tiles first
    const int bh = blockIdx.y;
    const int b = bh >> 4, h = bh & 15;
    const int q0 = qt * 64;
    const __half* base = qkv + (size_t)(b * Tt) * C3;
    const int qcol = h * HDt, kcol = Ct + h * HDt;
    const int wr0 = w * 16;
    // scale * log2(e): softmax tracked in exp2 domain
    const float scale2 = 0.0883883476483184f * 1.4426950408889634f;

    // per-lane ldmatrix.x4 offset for K fragments (nt-pair layout)
    const uint32_t k_loff =
        (uint32_t)(((lane >> 4) & 1) * 8 + (lane & 7)) * KROWB +
        ((lane >> 3) & 1) * 16;
    // per-lane ldmatrix.x4.trans offset for V (nt-pair per x4)
    const uint32_t v_loff =
        (uint32_t)(lane & 15) * KROWB + ((lane >> 4) & 1) * 16;

    // ---- Stage Q (one 64-row pass through buf1's K region), frags to regs
    uint32_t qf[8][4];
    {
        const uint32_t qstage = sbase + KVSTG * 4;    // buf1 K area
        uint32_t* Qs = sm + KVSTG;
#pragma unroll
        for (int i = 0; i < 8; ++i) {
            int id = tid + i * 128;
            int r = id >> 4, c = id & 15;
            cpasync16(qstage + (uint32_t)r * KROWB + c * 16,
                      base + (size_t)(q0 + r) * C3 + qcol + c * 8);
        }
        cp_commit(); cp_wait0();
        __syncthreads();
        {
            int rl = wr0 + g;
#pragma unroll
            for (int kk = 0; kk < 8; ++kk) {
                int a0 = rl * KVST + kk * 8 + tg;
                int a1 = (rl + 8) * KVST + kk * 8 + tg;
                qf[kk][0] = Qs[a0];
                qf[kk][1] = Qs[a1];
                qf[kk][2] = Qs[a0 + 4];
                qf[kk][3] = Qs[a1 + 4];
            }
        }
        __syncthreads();
    }

    auto issue_kv = [&](int j, int s) {
        const uint32_t stK = sbase + (uint32_t)s * KVSTG * 4;
        const uint32_t stV = stK + KV_U32 * 4;
        const int kv0 = j * 64;
#pragma unroll
        for (int i = 0; i < 8; ++i) {
            int id = tid + i * 128;
            int r = id >> 4, c = id & 15;
            uint32_t d = (uint32_t)r * KROWB + c * 16;
            const __half* kp = base + (size_t)(kv0 + r) * C3 + kcol + c * 8;
            cpasync16(stK + d, kp);
            cpasync16(stV + d, kp + Ct);
        }
    };

    float m_a = -1e30f, m_b = -1e30f, l_a = 0.f, l_b = 0.f;
    float o[16][4];
#pragma unroll
    for (int nt = 0; nt < 16; ++nt)
#pragma unroll
        for (int q = 0; q < 4; ++q) o[nt][q] = 0.f;

    const int njt = qt + 1;
    issue_kv(0, 0); cp_commit();
    cp_wait0();
    __syncthreads();

    for (int j = 0; j < njt; ++j) {
        if (j + 1 < njt) issue_kv(j + 1, (j + 1) & 1);
        cp_commit();

        const int kv0 = j * 64;
        const uint32_t kbyte = sbase + (j & 1) * KVSTG * 4;
        const uint32_t vbyte = kbyte + KV_U32 * 4;
        const uint32_t aK = kbyte + k_loff;
        const uint32_t aV = vbyte + v_loff;

        if (kv0 <= q0 + wr0 + 15) {          // warp-level causal skip
            float s[8][4];
#pragma unroll
            for (int nt = 0; nt < 8; ++nt)
#pragma unroll
                for (int q = 0; q < 4; ++q) s[nt][q] = 0.f;
            // S = Q @ K^T : 8 k-chunks x 4 nt-pairs (ldmatrix.x4 each)
#pragma unroll
            for (int kk = 0; kk < 8; ++kk) {
#pragma unroll
                for (int p = 0; p < 4; ++p) {
                    uint32_t b0[2], b1[2];
                    ldsm_x4(b0[0], b0[1], b1[0], b1[1],
                            aK + (uint32_t)p * (16 * KROWB) + kk * 32);
                    mma16f(s[2 * p],     qf[kk], b0);
                    mma16f(s[2 * p + 1], qf[kk], b1);
                }
            }

            // scale into exp2 domain
#pragma unroll
            for (int nt = 0; nt < 8; ++nt)
#pragma unroll
                for (int q = 0; q < 4; ++q) s[nt][q] *= scale2;

            if (kv0 + 63 > q0 + wr0) {       // diagonal tile: mask
                int ra = q0 + wr0 + g, rb = ra + 8;
#pragma unroll
                for (int nt = 0; nt < 8; ++nt) {
                    int c0 = kv0 + nt * 8 + tg * 2;
                    if (c0     > ra) s[nt][0] = -1e30f;
                    if (c0 + 1 > ra) s[nt][1] = -1e30f;
                    if (c0     > rb) s[nt][2] = -1e30f;
                    if (c0 + 1 > rb) s[nt][3] = -1e30f;
                }
            }

            // online softmax (exp2 domain)
            float tma = -1e30f, tmb = -1e30f;
#pragma unroll
            for (int nt = 0; nt < 8; ++nt) {
                tma = fmaxf(tma, fmaxf(s[nt][0], s[nt][1]));
                tmb = fmaxf(tmb, fmaxf(s[nt][2], s[nt][3]));
            }
            tma = fmaxf(tma, __shfl_xor_sync(0xffffffffu, tma, 1));
            tma = fmaxf(tma, __shfl_xor_sync(0xffffffffu, tma, 2));
            tmb = fmaxf(tmb, __shfl_xor_sync(0xffffffffu, tmb, 1));
            tmb = fmaxf(tmb, __shfl_xor_sync(0xffffffffu, tmb, 2));
            float mna = fmaxf(m_a, tma), mnb = fmaxf(m_b, tmb);
            float aa = fexp2(m_a - mna), ab = fexp2(m_b - mnb);
            float rsa = 0.f, rsb = 0.f;
#pragma unroll
            for (int nt = 0; nt < 8; ++nt) {
                s[nt][0] = fexp2(s[nt][0] - mna);
                s[nt][1] = fexp2(s[nt][1] - mna);
                s[nt][2] = fexp2(s[nt][2] - mnb);
                s[nt][3] = fexp2(s[nt][3] - mnb);
                rsa += s[nt][0] + s[nt][1];
                rsb += s[nt][2] + s[nt][3];
            }
            rsa += __shfl_xor_sync(0xffffffffu, rsa, 1);
            rsa += __shfl_xor_sync(0xffffffffu, rsa, 2);
            rsb += __shfl_xor_sync(0xffffffffu, rsb, 1);
            rsb += __shfl_xor_sync(0xffffffffu, rsb, 2);
            l_a = l_a * aa + rsa;
            l_b = l_b * ab + rsb;
            m_a = mna;
            m_b = mnb;
#pragma unroll
            for (int nt = 0; nt < 16; ++nt) {
                o[nt][0] *= aa; o[nt][1] *= aa;
                o[nt][2] *= ab; o[nt][3] *= ab;
            }

            // O += P @ V : P repacked in registers, V via ldmatrix.x4.trans
#pragma unroll
            for (int kk = 0; kk < 4; ++kk) {
                uint32_t pa[4];
                pa[0] = packh2(s[2 * kk][0],     s[2 * kk][1]);
                pa[1] = packh2(s[2 * kk][2],     s[2 * kk][3]);
                pa[2] = packh2(s[2 * kk + 1][0], s[2 * kk + 1][1]);
                pa[3] = packh2(s[2 * kk + 1][2], s[2 * kk + 1][3]);
                uint32_t vrow = aV + (uint32_t)(kk * 16) * KROWB;
#pragma unroll
                for (int p = 0; p < 8; ++p) {
                    uint32_t b0[2], b1[2];
                    ldsm_x4_t(b0[0], b0[1], b1[0], b1[1], vrow + p * 32);
                    mma16f(o[2 * p],     pa, b0);
                    mma16f(o[2 * p + 1], pa, b1);
                }
            }
        }

        cp_wait0();          // tile j+1 landed (overlapped with compute)
        __syncthreads();     // single barrier per kv tile (4 warps)
    }

    // epilogue: normalize, fp16 y
    float inva = 1.f / l_a, invb = 1.f / l_b;
    int rt = b * Tt + q0 + wr0 + g;
#pragma unroll
    for (int nt = 0; nt < 16; ++nt) {
        int c = h * HDt + nt * 8 + tg * 2;
        *(uint32_t*)(y + (size_t)rt * Ct + c) =
            packh2(o[nt][0] * inva, o[nt][1] * inva);
        *(uint32_t*)(y + (size_t)(rt + 8) * Ct + c) =
            packh2(o[nt][2] * invb, o[nt][3] * invb);
    }
}

// ---------------------------------------------------------------------------
extern "C" void kernel_launch(void* const* d_in, const int* in_sizes, int n_in,
                              void* d_out, int out_size)
{
    const float* x     = (const float*)d_in[0];
    const float* rope  = (const float*)d_in[1];
    const float* Wqkv  = (const float*)d_in[2];
    const float* Wproj = (const float*)d_in[3];
    float* out = (float*)d_out;

    __half *qkv, *xh, *wqh, *wql, *wph, *wpl, *y;
    cudaGetSymbolAddress((void**)&qkv, g_qkv);
    cudaGetSymbolAddress((void**)&xh, g_xh);
    cudaGetSymbolAddress((void**)&wqh, g_wqh);
    cudaGetSymbolAddress((void**)&wql, g_wql);
    cudaGetSymbolAddress((void**)&wph, g_wph);
    cudaGetSymbolAddress((void**)&wpl, g_wpl);
    cudaGetSymbolAddress((void**)&y, g_y);

    cudaFuncSetAttribute(gemm_fp16x2, cudaFuncAttributeMaxDynamicSharedMemorySize,
                         GEMM_SMEM);
    cudaFuncSetAttribute(flash_kernel, cudaFuncAttributeMaxDynamicSharedMemorySize,
                         FLASH_SMEM);

    // 0) pre-pass: x -> fp16 ; W -> fp16 hi/lo transposed
    {
        size_t nx = (size_t)MTOT * Ct;
        tohalf_kernel<<<(unsigned)((nx + 255) / 256), 256>>>(x, xh, nx);
        split_transpose_kernel<<<dim3(C3 / 32, Ct / 32), dim3(32, 8)>>>(Wqkv, wqh, wql, Ct, C3);
        split_transpose_kernel<<<dim3(Ct / 32, Ct / 32), dim3(32, 8)>>>(Wproj, wph, wpl, Ct, Ct);
    }

    // 1) qkv = x @ Wqkv + fused RoPE, fp16 out  (M=8192, N=6144, K=2048)
    //    (lo pass active only for q,k column CTAs)
    gemm_fp16x2<<<dim3(C3 / 128, MTOT / 128), 128, GEMM_SMEM>>>(
        xh, wqh, wql, qkv, MTOT, C3, Ct, rope);

    // 2) flash attention -> y (fp16), 64 q-rows/CTA, 2 CTAs/SM
    flash_kernel<<<dim3(Tt / 64, Bt * Ht), 128, FLASH_SMEM>>>(qkv, y);

    // 3) out = y @ Wproj, fp32 out, single-pass  (M=8192, N=2048, K=2048)
    gemm_fp16x2<<<dim3(Ct / 128, MTOT / 128), 128, GEMM_SMEM>>>(
        y, wph, wpl, out, MTOT, Ct, Ct, nullptr);
}